// round 12
// baseline (speedup 1.0000x reference)
#include <cuda_runtime.h>
#include <cuda_bf16.h>
#include <cstdint>
#include <math.h>

// ---------------------------------------------------------------------------
// Problem constants
// ---------------------------------------------------------------------------
static constexpr int kB = 8;
static constexpr int kS = 2048;
static constexpr int kD = 256;
static constexpr int kM = kB * kS;
static constexpr int QCH = 64;       // colsum: 32 rows per chunk
static constexpr int N_KCHUNK = 32;  // output split over keys
static constexpr int NXT = kS / 256; // 8 n-tiles per batch row

// Scratch (static device memory)
// Blocked layout: block = [128 rows x 32 cols] = 16KB, SW128-swizzled.
__device__ float g_Nb[kM * kD];                        // tf32-rounded nodes, blocked
__device__ float g_Wh[3 * kD * kD];                    // weight hi, blocked (q,k,v)
__device__ float g_Wl[2 * kD * kD];                    // weight lo, blocked (q,k)
__device__ float g_Qb[kB * kS * kD];                   // tf32 q, blocked
__device__ float g_Kb[kB * kS * kD];                   // tf32 k, blocked
__device__ float g_V[kB * kS * kD];                    // fp32 v, row-major
__device__ __nv_bfloat16 g_E[(size_t)kB * kS * kS];    // exp scores (bf16)
__device__ float g_rpart[NXT * kB * kS];
__device__ float g_wpart[QCH * kB * kS];
__device__ float g_opart[N_KCHUNK * kB * kD];

#if defined(__CUDA_ARCH__) && defined(__CUDA_ARCH_FEAT_SM103_ALL)
#define HAS_TCGEN05 1
#else
#define HAS_TCGEN05 0
#endif

#define SMEM_SWIZZLE_128B(byte_offset) \
    ((byte_offset) ^ (((byte_offset) >> 3) & 0x70))

__device__ __forceinline__ uint32_t smem_to_u32_gen(const void* p) {
    uint32_t a;
    asm("{ .reg .u64 t; cvta.to.shared.u64 t, %1; cvt.u32.u64 %0, t; }"
        : "=r"(a) : "l"(p));
    return a;
}

__device__ __forceinline__ float to_tf32(float x) {
    float y;
    asm("cvt.rna.tf32.f32 %0, %1;" : "=f"(y) : "f"(x));
    return y;
}

__device__ __forceinline__ uint32_t pack_bf16x2(float lo, float hi) {
    uint32_t r;
    asm("cvt.rn.bf16x2.f32 %0, %1, %2;" : "=r"(r) : "f"(hi), "f"(lo));
    return r;
}

// float-index offset of element (r in [0,128), c in [0,32)) in blocked layout
__device__ __forceinline__ size_t qk_blk_off(int gmtile, int kchunk, int r, int c) {
    uint32_t byte = (uint32_t)(r * 128 + (c >> 2) * 16);
    uint32_t sw = SMEM_SWIZZLE_128B(byte) + (uint32_t)(c & 3) * 4;
    return ((size_t)(gmtile * 8 + kchunk) << 12) + (sw >> 2);
}

#if HAS_TCGEN05
__device__ __forceinline__ uint32_t elect_one_pred() {
    uint32_t pred;
    asm volatile(
        "{\n\t.reg .pred p;\n\t"
        "elect.sync _|p, 0xFFFFFFFF;\n\t"
        "selp.b32 %0, 1, 0, p;\n\t}"
        : "=r"(pred));
    return pred;
}

__device__ __forceinline__ uint32_t cluster_rank() {
    uint32_t r;
    asm("mov.u32 %0, %%cluster_ctarank;" : "=r"(r));
    return r;
}

#define CLUSTER_SYNC() do { \
    asm volatile("barrier.cluster.arrive.aligned;" ::: "memory"); \
    asm volatile("barrier.cluster.wait.aligned;" ::: "memory"); \
} while (0)

#define TCGEN05_ALLOC(smem_result_addr, nCols) \
    asm volatile("tcgen05.alloc.cta_group::1.sync.aligned.shared::cta.b32 [%0], %1;" \
                 :: "r"((uint32_t)(smem_result_addr)), "r"((uint32_t)(nCols)) : "memory")
#define TCGEN05_DEALLOC(tmem_addr, nCols) \
    asm volatile("tcgen05.dealloc.cta_group::1.sync.aligned.b32 %0, %1;" \
                 :: "r"(tmem_addr), "r"((uint32_t)(nCols)))
#define TCGEN05_RELINQUISH() \
    asm volatile("tcgen05.relinquish_alloc_permit.cta_group::1.sync.aligned;")
#define TCGEN05_COMMIT(mbar_smem_addr) \
    asm volatile("tcgen05.commit.cta_group::1.mbarrier::arrive::one.shared::cluster.b64 [%0];" \
                 :: "r"((uint32_t)(mbar_smem_addr)) : "memory")
#define TCGEN05_COMMIT_MC(mbar_smem_addr, cta_mask) \
    asm volatile("tcgen05.commit.cta_group::1.mbarrier::arrive::one.shared::cluster.multicast::cluster.b64 [%0], %1;" \
                 :: "r"((uint32_t)(mbar_smem_addr)), "h"((uint16_t)(cta_mask)) : "memory")
#define TCGEN05_FENCE_AFTER() \
    asm volatile("tcgen05.fence::after_thread_sync;" ::: "memory")
#define TCGEN05_WAIT_LD() \
    asm volatile("tcgen05.wait::ld.sync.aligned;" ::: "memory")
#define MBARRIER_INIT(mbar_smem_addr, count) \
    asm volatile("mbarrier.init.shared.b64 [%0], %1;" \
                 :: "r"((uint32_t)(mbar_smem_addr)), "r"((uint32_t)(count)) : "memory")
#define MBARRIER_EXPECT_TX(mbar_smem_addr, tx_bytes) \
    asm volatile("mbarrier.arrive.expect_tx.shared.b64 _, [%0], %1;" \
                 :: "r"((uint32_t)(mbar_smem_addr)), "r"((uint32_t)(tx_bytes)) : "memory")

#define MBARRIER_WAIT_PARITY(mbar_smem_addr, phase_parity) do { \
    uint32_t _mbar = (uint32_t)(mbar_smem_addr); \
    uint32_t _parity = (uint32_t)(phase_parity); \
    uint32_t _done; \
    asm volatile( \
        "{\n\t.reg .pred p;\n\t" \
        "mbarrier.try_wait.parity.acquire.cta.shared::cta.b64 p, [%1], %2;\n\t" \
        "selp.b32 %0, 1, 0, p;\n\t}" \
        : "=r"(_done) : "r"(_mbar), "r"(_parity) : "memory"); \
    if (!_done) { \
        asm volatile( \
            "{\n\t.reg .pred P1;\n\t" \
            "WAIT_LOOP_%=:\n\t" \
            "mbarrier.try_wait.parity.acquire.cta.shared::cta.b64 P1, [%0], %1, 0x989680;\n\t" \
            "@P1 bra.uni WAIT_DONE_%=;\n\t" \
            "bra.uni WAIT_LOOP_%=;\n\t" \
            "WAIT_DONE_%=:\n\t}" \
            :: "r"(_mbar), "r"(_parity) : "memory"); \
    } \
} while(0)

#define TCGEN05_LD_32X32B_X32(r, tmem_addr) \
    asm volatile( \
        "tcgen05.ld.sync.aligned.32x32b.x32.b32 " \
        "{%0, %1, %2, %3, %4, %5, %6, %7, " \
        " %8, %9, %10, %11, %12, %13, %14, %15, " \
        " %16, %17, %18, %19, %20, %21, %22, %23, " \
        " %24, %25, %26, %27, %28, %29, %30, %31}, [%32];" \
        : "=r"((r)[0]),  "=r"((r)[1]),  "=r"((r)[2]),  "=r"((r)[3]), \
          "=r"((r)[4]),  "=r"((r)[5]),  "=r"((r)[6]),  "=r"((r)[7]), \
          "=r"((r)[8]),  "=r"((r)[9]),  "=r"((r)[10]), "=r"((r)[11]), \
          "=r"((r)[12]), "=r"((r)[13]), "=r"((r)[14]), "=r"((r)[15]), \
          "=r"((r)[16]), "=r"((r)[17]), "=r"((r)[18]), "=r"((r)[19]), \
          "=r"((r)[20]), "=r"((r)[21]), "=r"((r)[22]), "=r"((r)[23]), \
          "=r"((r)[24]), "=r"((r)[25]), "=r"((r)[26]), "=r"((r)[27]), \
          "=r"((r)[28]), "=r"((r)[29]), "=r"((r)[30]), "=r"((r)[31]) \
        : "r"(tmem_addr))

#define TCGEN05_MMA_TF32_SS(d_tmem, a_desc, b_desc, idesc, enable_d) do { \
    uint32_t _en = (enable_d) ? 1u : 0u; \
    uint32_t _zero = 0u; \
    asm volatile( \
        "{\n\t.reg .pred p;\n\t" \
        "setp.ne.u32 p, %5, 0;\n\t" \
        "tcgen05.mma.cta_group::1.kind::tf32 [%0], %1, %2, %3, {%4, %4, %4, %4}, p;\n\t" \
        "}" \
        :: "r"(d_tmem), "l"(a_desc), "l"(b_desc), "r"(idesc), "r"(_zero), "r"(_en) \
        : "memory"); \
} while(0)

static constexpr uint64_t SMEM_DESC_BASE_SW128 =
    (uint64_t(2)  << 61) | (uint64_t(1) << 46) | (uint64_t(64) << 32) | (uint64_t(1) << 16);
#define MAKE_SMEM_DESC(base_addr) \
    (SMEM_DESC_BASE_SW128 | ((uint64_t)((base_addr) >> 4) & 0x3FFF))

#define CP_ASYNC_BULK(dst_smem, src_gmem, bytes, mbar) \
    asm volatile("cp.async.bulk.shared::cta.global.mbarrier::complete_tx::bytes " \
                 "[%0], [%1], %2, [%3];" \
                 :: "r"((uint32_t)(dst_smem)), "l"(src_gmem), \
                    "r"((uint32_t)(bytes)), "r"((uint32_t)(mbar)) : "memory")

#define CP_ASYNC_BULK_MC(dst_smem, src_gmem, bytes, mbar, cta_mask) \
    asm volatile("cp.async.bulk.shared::cluster.global.mbarrier::complete_tx::bytes.multicast::cluster " \
                 "[%0], [%1], %2, [%3], %4;" \
                 :: "r"((uint32_t)(dst_smem)), "l"(src_gmem), \
                    "r"((uint32_t)(bytes)), "r"((uint32_t)(mbar)), \
                    "h"((uint16_t)(cta_mask)) : "memory")

// IDESC: tf32, F32 accum
static constexpr uint32_t IDESC_128x256 =
    (1u << 4) | (2u << 7) | (2u << 10) | ((256 / 8) << 17) | ((128 / 16) << 24);
static constexpr uint32_t IDESC_128x128 =
    (1u << 4) | (2u << 7) | (2u << 10) | ((128 / 8) << 17) | ((128 / 16) << 24);
#endif  // HAS_TCGEN05

// ---------------------------------------------------------------------------
// Prep 1: nodes -> tf32-rounded, blocked-swizzled. grid (8, kM/128).
// ---------------------------------------------------------------------------
__global__ __launch_bounds__(256)
void nodes_prep(const float* __restrict__ src, float* __restrict__ Nb)
{
    const int kc = blockIdx.x;
    const int mt = blockIdx.y;
    const int tid = threadIdx.x;
    float* blk = Nb + (((size_t)mt * 8 + kc) << 12);
#pragma unroll
    for (int t = 0; t < 4; t++) {
        int idx = tid + t * 256;
        int row = idx >> 3, c4 = idx & 7;
        float4 v = *(const float4*)(src + (size_t)(mt * 128 + row) * kD + kc * 32 + c4 * 4);
        v.x = to_tf32(v.x); v.y = to_tf32(v.y);
        v.z = to_tf32(v.z); v.w = to_tf32(v.w);
        uint32_t sw = SMEM_SWIZZLE_128B((uint32_t)(row * 128 + c4 * 16));
        *(float4*)((char*)blk + sw) = v;
    }
}

// ---------------------------------------------------------------------------
// Prep 2: weights -> (hi, lo) tf32 split, blocked. grid (8, 2, 3).
// ---------------------------------------------------------------------------
__global__ __launch_bounds__(256)
void wsplit_prep(const float* __restrict__ Wq, const float* __restrict__ Wk,
                 const float* __restrict__ Wv,
                 float* __restrict__ Wh, float* __restrict__ Wl)
{
    const int kc = blockIdx.x;
    const int mt = blockIdx.y;
    const int w  = blockIdx.z;
    const int tid = threadIdx.x;
    const float* W = (w == 0) ? Wq : (w == 1) ? Wk : Wv;
    float* bh = Wh + (size_t)w * (kD * kD) + (((size_t)mt * 8 + kc) << 12);
    float* bl = (w < 2) ? Wl + (size_t)w * (kD * kD) + (((size_t)mt * 8 + kc) << 12)
                        : nullptr;
#pragma unroll
    for (int t = 0; t < 4; t++) {
        int idx = tid + t * 256;
        int row = idx >> 3, c4 = idx & 7;
        float4 v = *(const float4*)(W + (size_t)(mt * 128 + row) * kD + kc * 32 + c4 * 4);
        float4 h, l;
        h.x = to_tf32(v.x); l.x = to_tf32(v.x - h.x);
        h.y = to_tf32(v.y); l.y = to_tf32(v.y - h.y);
        h.z = to_tf32(v.z); l.z = to_tf32(v.z - h.z);
        h.w = to_tf32(v.w); l.w = to_tf32(v.w - h.w);
        uint32_t sw = SMEM_SWIZZLE_128B((uint32_t)(row * 128 + c4 * 16));
        *(float4*)((char*)bh + sw) = h;
        if (bl) *(float4*)((char*)bl + sw) = l;
    }
}

// ---------------------------------------------------------------------------
// Pipelined projection GEMM, BM=128, BN=128, grid (2 nx, 128 my, 3 w).
// ---------------------------------------------------------------------------
static constexpr int PJ_STAGE = 49152;
static constexpr int PJ_SMEM = 2048 + 2 * PJ_STAGE;   // 100352

__global__ __launch_bounds__(256)
void proj_gemm(const float* __restrict__ Nb,
               const float* __restrict__ Wh, const float* __restrict__ Wl,
               const float* __restrict__ b0, const float* __restrict__ b1,
               const float* __restrict__ b2,
               float* __restrict__ C0, float* __restrict__ C1,
               float* __restrict__ C2)
{
    extern __shared__ __align__(1024) char smem[];
    const int tid = threadIdx.x;
    const int nx = blockIdx.x;
    const int my = blockIdx.y;
    const int w  = blockIdx.z;
    const float* bias = (w == 0) ? b0 : (w == 1) ? b1 : b2;
    float* C = (w == 0) ? C0 : (w == 1) ? C1 : C2;
    const bool two_pass = (w < 2);
    const float* WhB = Wh + (size_t)w * (kD * kD);
    const float* WlB = Wl + (size_t)w * (kD * kD);
    const int bn = nx * 128;
    const int bm = my * 128;

#if HAS_TCGEN05
    const uint32_t sb = smem_to_u32_gen(smem);
    const uint32_t m_done = sb + 32;
    float* s_bias = (float*)(smem + 1024);
    const int wid = tid >> 5;

    if (wid == 0) { TCGEN05_ALLOC(sb + 40, 128); TCGEN05_RELINQUISH(); }
    if (tid == 0) {
        MBARRIER_INIT(sb + 0, 1);
        MBARRIER_INIT(sb + 8, 1);
        MBARRIER_INIT(sb + 16, 1);
        MBARRIER_INIT(sb + 24, 1);
        MBARRIER_INIT(m_done, 1);
    }
    if (tid < 128) s_bias[tid] = bias[bn + tid];
    __syncthreads();
    const uint32_t tmem = *(volatile uint32_t*)(smem + 40);

    uint64_t dA[2], dBh[2], dBl[2];
#pragma unroll
    for (int s = 0; s < 2; s++) {
        uint32_t base = sb + 2048 + s * PJ_STAGE;
        dA[s]  = MAKE_SMEM_DESC(base);
        dBh[s] = MAKE_SMEM_DESC(base + 16384);
        dBl[s] = MAKE_SMEM_DESC(base + 32768);
    }

    const uint32_t tx_bytes = two_pass ? 49152u : 32768u;

    if (wid == 1) {
        if (elect_one_pred()) {
            for (int c = 0; c < 8; c++) {
                const int s = c & 1;
                const int i = c >> 1;
                const uint32_t m_full = sb + s * 8;
                const uint32_t m_emp  = sb + 16 + s * 8;
                const uint32_t st = sb + 2048 + s * PJ_STAGE;
                MBARRIER_WAIT_PARITY(m_emp, 1 ^ (i & 1));
                MBARRIER_EXPECT_TX(m_full, tx_bytes);
                CP_ASYNC_BULK(st,
                              Nb + (((size_t)my * 8 + c) << 12), 16384, m_full);
                CP_ASYNC_BULK(st + 16384,
                              WhB + (((size_t)nx * 8 + c) << 12), 16384, m_full);
                if (two_pass)
                    CP_ASYNC_BULK(st + 32768,
                                  WlB + (((size_t)nx * 8 + c) << 12), 16384, m_full);
            }
        }
    } else if (wid == 0) {
        if (elect_one_pred()) {
            for (int c = 0; c < 8; c++) {
                const int s = c & 1;
                const int i = c >> 1;
                const uint32_t m_full = sb + s * 8;
                const uint32_t m_emp  = sb + 16 + s * 8;
                MBARRIER_WAIT_PARITY(m_full, i & 1);
#pragma unroll
                for (int k = 0; k < 4; k++)
                    TCGEN05_MMA_TF32_SS(tmem, dA[s] + k * 2, dBh[s] + k * 2,
                                        IDESC_128x128, (c > 0) || (k > 0));
                if (two_pass) {
#pragma unroll
                    for (int k = 0; k < 4; k++)
                        TCGEN05_MMA_TF32_SS(tmem, dA[s] + k * 2, dBl[s] + k * 2,
                                            IDESC_128x128, true);
                }
                TCGEN05_COMMIT(m_emp);
            }
            TCGEN05_COMMIT(m_done);
        }
    }

    MBARRIER_WAIT_PARITY(m_done, 0);
    TCGEN05_FENCE_AFTER();

    {
        const int lane = tid & 31;
        const int half = wid >> 2;
        const int mloc = (wid & 3) * 32 + lane;
        const int m = bm + mloc;
#pragma unroll
        for (int g = 0; g < 2; g++) {
            const int col0 = half * 64 + g * 32;
            uint32_t r[32];
            TCGEN05_LD_32X32B_X32(r, tmem + col0);
            TCGEN05_WAIT_LD();
            if (two_pass) {
#pragma unroll
                for (int j = 0; j < 32; j++)
                    r[j] = __float_as_uint(
                        to_tf32(__uint_as_float(r[j]) + s_bias[col0 + j]));
                float* blk = C + (((size_t)(m >> 7) * 8 + nx * 4 + half * 2 + g) << 12);
#pragma unroll
                for (int j = 0; j < 8; j++) {
                    uint32_t sw = SMEM_SWIZZLE_128B((uint32_t)(mloc * 128 + j * 16));
                    *(float4*)((char*)blk + sw) = *(float4*)&r[j * 4];
                }
            } else {
#pragma unroll
                for (int j = 0; j < 32; j++)
                    r[j] = __float_as_uint(__uint_as_float(r[j]) + s_bias[col0 + j]);
                float* crow = C + (size_t)m * kD + bn + col0;
#pragma unroll
                for (int j = 0; j < 8; j++)
                    *(float4*)&crow[j * 4] = *(float4*)&r[j * 4];
            }
        }
    }
    __syncthreads();
    if (wid == 0) TCGEN05_DEALLOC(tmem, 128);

#else
    // SIMT fallback
    constexpr int BK = 16, TM = 8, TN = 8;
    float* As = (float*)smem;
    float* Bs = As + BK * 128;
    const int tx = tid & 15, ty = tid >> 4;

    float acc[TM][TN];
#pragma unroll
    for (int i = 0; i < TM; i++)
#pragma unroll
        for (int j = 0; j < TN; j++) acc[i][j] = 0.0f;

    for (int k0 = 0; k0 < kD; k0 += BK) {
        __syncthreads();
        for (int li = tid; li < 128 * BK; li += 256) {
            int row = li / BK, kc = li % BK;
            size_t off = qk_blk_off(nx, (k0 + kc) >> 5, row, (k0 + kc) & 31);
            As[kc * 128 + row] =
                Nb[qk_blk_off(my, (k0 + kc) >> 5, row, (k0 + kc) & 31)];
            float bw = WhB[off];
            if (two_pass) bw += WlB[off];
            Bs[kc * 128 + row] = bw;
        }
        __syncthreads();
#pragma unroll
        for (int kk = 0; kk < BK; kk++) {
            float a[TM], bb[TN];
            *(float4*)&a[0]  = *(const float4*)&As[kk * 128 + ty * TM];
            *(float4*)&a[4]  = *(const float4*)&As[kk * 128 + ty * TM + 4];
            *(float4*)&bb[0] = *(const float4*)&Bs[kk * 128 + tx * TN];
            *(float4*)&bb[4] = *(const float4*)&Bs[kk * 128 + tx * TN + 4];
#pragma unroll
            for (int i = 0; i < TM; i++)
#pragma unroll
                for (int j = 0; j < TN; j++)
                    acc[i][j] = fmaf(a[i], bb[j], acc[i][j]);
        }
    }
    const int row0 = bm + ty * TM, col0 = bn + tx * TN;
#pragma unroll
    for (int i = 0; i < TM; i++)
#pragma unroll
        for (int j = 0; j < TN; j++) {
            float v = acc[i][j] + bias[col0 + j];
            int m = row0 + i, n = col0 + j;
            if (two_pass)
                C[qk_blk_off(m >> 7, n >> 5, m & 127, n & 31)] = to_tf32(v);
            else
                C[(size_t)m * kD + n] = v;
        }
#endif
}

// ---------------------------------------------------------------------------
// Scores GEMM with 2-CTA cluster K-multicast.
// grid (16 my, 8 nx, 8 bz), cluster (2,1,1): rank pairs share (bz,nx) K tiles.
// Each rank bulk-loads ONE 16KB K half per chunk and multicasts to both.
// E[b,m,n] = exp((q.k)/16) * maskfac(n) bf16, + rowsum partials.
// smem ctrl: full0@0 full1@8 emp0@16 emp1@24 done@32 tmem@40,
//            rs2[128]@256, maskf[256]@1024
// stages: 2 x 48KB {Q 16K | K 32K}   total 100352 -> 2 CTAs/SM
// ---------------------------------------------------------------------------
static constexpr int SC_STAGE = 49152;
static constexpr int SC_SMEM = 2048 + 2 * SC_STAGE;   // 100352

__global__ __launch_bounds__(256) __cluster_dims__(2, 1, 1)
void score_gemm(const float* __restrict__ Qb, const float* __restrict__ Kb,
                const int* __restrict__ mask, __nv_bfloat16* __restrict__ E,
                float* __restrict__ rpart, float scale)
{
    extern __shared__ __align__(1024) char smem[];
    const int tid = threadIdx.x;
    const int bz = blockIdx.z;
    __nv_bfloat16* C = E + (size_t)bz * kS * kS;
    const int* mk = mask + (size_t)bz * kS;

    const int my = blockIdx.x;          // m tile (128 rows); cluster pairs on x
    const int nx = blockIdx.y;          // n tile (256 cols)
    const int bm = my * 128;
    const int bn = nx * 256;

#if HAS_TCGEN05
    const uint32_t sb = smem_to_u32_gen(smem);
    const uint32_t m_done = sb + 32;
    float* s_rs2 = (float*)(smem + 256);
    float* s_mf  = (float*)(smem + 1024);
    const int wid = tid >> 5;
    const uint32_t rank = cluster_rank();

    if (wid == 0) { TCGEN05_ALLOC(sb + 40, 256); TCGEN05_RELINQUISH(); }
    if (tid == 0) {
        MBARRIER_INIT(sb + 0, 1);    // full0
        MBARRIER_INIT(sb + 8, 1);    // full1
        MBARRIER_INIT(sb + 16, 2);   // empty0 (commits from both consumers)
        MBARRIER_INIT(sb + 24, 2);   // empty1
        MBARRIER_INIT(m_done, 1);
    }
    s_mf[tid] = (mk[bn + tid] != 0) ? 1.0f : 0.0f;
    __syncthreads();
    CLUSTER_SYNC();                  // peer mbarriers ready before multicast
    const uint32_t tmem = *(volatile uint32_t*)(smem + 40);

    uint64_t dA[2], dB[2];
#pragma unroll
    for (int s = 0; s < 2; s++) {
        uint32_t base = sb + 2048 + s * SC_STAGE;
        dA[s] = MAKE_SMEM_DESC(base);
        dB[s] = MAKE_SMEM_DESC(base + 16384);
    }

    const int amt  = bz * 16 + my;
    const int bmt0 = bz * 16 + nx * 2;
    const int kblk = bmt0 + (int)rank;   // this rank's K half

    if (wid == 1) {
        if (elect_one_pred()) {
            for (int c = 0; c < 8; c++) {
                const int s = c & 1;
                const int i = c >> 1;
                const uint32_t m_full = sb + s * 8;
                const uint32_t m_emp  = sb + 16 + s * 8;
                const uint32_t st = sb + 2048 + s * SC_STAGE;
                MBARRIER_WAIT_PARITY(m_emp, 1 ^ (i & 1));
                MBARRIER_EXPECT_TX(m_full, SC_STAGE);   // Q 16K + K 2x16K
                CP_ASYNC_BULK(st,
                              Qb + (((size_t)amt * 8 + c) << 12), 16384, m_full);
                CP_ASYNC_BULK_MC(st + 16384 + rank * 16384,
                                 Kb + (((size_t)kblk * 8 + c) << 12), 16384,
                                 m_full, 0x3);
            }
        }
    } else if (wid == 0) {
        if (elect_one_pred()) {
            for (int c = 0; c < 8; c++) {
                const int s = c & 1;
                const int i = c >> 1;
                const uint32_t m_full = sb + s * 8;
                const uint32_t m_emp  = sb + 16 + s * 8;
                MBARRIER_WAIT_PARITY(m_full, i & 1);
#pragma unroll
                for (int k = 0; k < 4; k++)
                    TCGEN05_MMA_TF32_SS(tmem, dA[s] + k * 2, dB[s] + k * 2,
                                        IDESC_128x256, (c > 0) || (k > 0));
                TCGEN05_COMMIT_MC(m_emp, 0x3);   // release stage in BOTH CTAs
            }
            TCGEN05_COMMIT(m_done);
        }
    }

    MBARRIER_WAIT_PARITY(m_done, 0);
    TCGEN05_FENCE_AFTER();

    // Epilogue: warps 0-3 keys 0-127, warps 4-7 keys 128-255 (same q rows).
    {
        const int lane = tid & 31;
        const int half = wid >> 2;
        const int qrow = (wid & 3) * 32 + lane;
        const int m = bm + qrow;
        __nv_bfloat16* crow = C + (size_t)m * kS + bn + half * 128;
        float rs = 0.0f;
#pragma unroll
        for (int g = 0; g < 4; g++) {
            const int col0 = half * 128 + g * 32;
            uint32_t r[32];
            TCGEN05_LD_32X32B_X32(r, tmem + col0);
            TCGEN05_WAIT_LD();
            float e[32];
#pragma unroll
            for (int j = 0; j < 32; j++) {
                e[j] = __expf(__uint_as_float(r[j]) * scale) * s_mf[col0 + j];
                rs += e[j];
            }
            uint32_t pk[16];
#pragma unroll
            for (int j = 0; j < 16; j++)
                pk[j] = pack_bf16x2(e[j * 2], e[j * 2 + 1]);
#pragma unroll
            for (int j = 0; j < 4; j++)
                *(uint4*)&crow[g * 32 + j * 8] = *(uint4*)&pk[j * 4];
        }
        if (half == 1) s_rs2[qrow] = rs;
        __syncthreads();
        if (half == 0)
            rpart[((size_t)nx * kB + bz) * kS + m] = rs + s_rs2[qrow];
    }
    __syncthreads();
    if (wid == 0) TCGEN05_DEALLOC(tmem, 256);
    CLUSTER_SYNC();                  // no CTA exits while peer traffic in flight

#else
    // SIMT fallback — reads blocked Q/K layout, writes bf16 E + rpart.
    constexpr int BK = 16, TM = 8, TN = 8;
    float* As = (float*)smem;
    float* Bs = As + BK * 128;
    const int tx = tid & 15, ty = tid >> 4;
    const int amt  = bz * 16 + my;
    const int bmt0 = bz * 16 + nx * 2;

    float rs[TM];
#pragma unroll
    for (int i = 0; i < TM; i++) rs[i] = 0.0f;

    for (int nh = 0; nh < 2; nh++) {
        const int bmtl = bmt0 + nh;
        float acc[TM][TN];
#pragma unroll
        for (int i = 0; i < TM; i++)
#pragma unroll
            for (int j = 0; j < TN; j++) acc[i][j] = 0.0f;

        for (int k0 = 0; k0 < kD; k0 += BK) {
            __syncthreads();
            for (int li = tid; li < 128 * BK; li += 256) {
                int row = li / BK, kc = li % BK;
                As[kc * 128 + row] =
                    Qb[qk_blk_off(amt, (k0 + kc) >> 5, row, (k0 + kc) & 31)];
                Bs[kc * 128 + row] =
                    Kb[qk_blk_off(bmtl, (k0 + kc) >> 5, row, (k0 + kc) & 31)];
            }
            __syncthreads();
#pragma unroll
            for (int kk = 0; kk < BK; kk++) {
                float a[TM], bb[TN];
                *(float4*)&a[0]  = *(const float4*)&As[kk * 128 + ty * TM];
                *(float4*)&a[4]  = *(const float4*)&As[kk * 128 + ty * TM + 4];
                *(float4*)&bb[0] = *(const float4*)&Bs[kk * 128 + tx * TN];
                *(float4*)&bb[4] = *(const float4*)&Bs[kk * 128 + tx * TN + 4];
#pragma unroll
                for (int i = 0; i < TM; i++)
#pragma unroll
                    for (int j = 0; j < TN; j++)
                        acc[i][j] = fmaf(a[i], bb[j], acc[i][j]);
            }
        }
        const int row0 = bm + ty * TM;
        const int col0 = bn + nh * 128 + tx * TN;
#pragma unroll
        for (int i = 0; i < TM; i++)
#pragma unroll
            for (int j = 0; j < TN; j++) {
                float e = __expf(acc[i][j] * scale)
                          * ((mk[col0 + j] != 0) ? 1.0f : 0.0f);
                C[(size_t)(row0 + i) * kS + col0 + j] = __float2bfloat16(e);
                rs[i] += e;
            }
        __syncthreads();
    }
#pragma unroll
    for (int i = 0; i < TM; i++) {
        float v = rs[i];
#pragma unroll
        for (int o = 8; o; o >>= 1) v += __shfl_xor_sync(0xffffffffu, v, o);
        if (tx == 0)
            rpart[((size_t)nx * kB + bz) * kS + bm + ty * TM + i] = v;
    }
#endif
}

// ---------------------------------------------------------------------------
// Column-sum stream over bf16 E with inline invr (from rpart partials).
// ---------------------------------------------------------------------------
__global__ __launch_bounds__(256)
void colsum_stream_kernel(const __nv_bfloat16* __restrict__ E,
                          const float* __restrict__ rpart,
                          float* __restrict__ wpart)
{
    __shared__ float s_inv[32];
    const int ch = blockIdx.x;
    const int b  = blockIdx.y;
    const int tid = threadIdx.x;

    if (tid < 32) {
        const size_t q = (size_t)b * kS + (size_t)ch * 32 + tid;
        float s = 0.0f;
#pragma unroll
        for (int c = 0; c < NXT; c++) s += rpart[(size_t)c * (kB * kS) + q];
        s_inv[tid] = 1.0f / s;
    }
    __syncthreads();

    const __nv_bfloat16* base = E + ((size_t)b * kS + (size_t)ch * 32) * kS;
    float wacc[8];
#pragma unroll
    for (int i = 0; i < 8; i++) wacc[i] = 0.0f;

    for (int r = 0; r < 32; r++) {
        const float s = s_inv[r];
        const __nv_bfloat16* p = base + (size_t)r * kS + tid * 8;
        uint4 v = *(const uint4*)p;
        const uint32_t pk[4] = {v.x, v.y, v.z, v.w};
#pragma unroll
        for (int i = 0; i < 4; i++) {
            float2 f = __bfloat1622float2(*(const __nv_bfloat162*)&pk[i]);
            wacc[i * 2]     = fmaf(f.x, s, wacc[i * 2]);
            wacc[i * 2 + 1] = fmaf(f.y, s, wacc[i * 2 + 1]);
        }
    }

    float* o = wpart + (size_t)ch * (kB * kS) + (size_t)b * kS + tid * 8;
    *(float4*)&o[0] = make_float4(wacc[0], wacc[1], wacc[2], wacc[3]);
    *(float4*)&o[4] = make_float4(wacc[4], wacc[5], wacc[6], wacc[7]);
}

// ---------------------------------------------------------------------------
// out_part: w segment reduced from wpart in-block, then o = sum_k w_k V[k,d].
// ---------------------------------------------------------------------------
__global__ __launch_bounds__(256)
void out_part_kernel(const float* __restrict__ wpart, const float* __restrict__ V,
                     float* __restrict__ opart)
{
    __shared__ float ws[64];
    const int chunk = blockIdx.x;
    const int b     = blockIdx.y;
    const int tid   = threadIdx.x;

    if (tid < 64) {
        const int key = chunk * 64 + tid;
        float s = 0.0f;
#pragma unroll 8
        for (int c = 0; c < QCH; c++)
            s += wpart[(size_t)c * (kB * kS) + (size_t)b * kS + key];
        ws[tid] = s;
    }
    __syncthreads();

    const float* vb = V + ((size_t)b * kS + (size_t)chunk * 64) * kD;
    float s = 0.0f;
#pragma unroll
    for (int k = 0; k < 64; k++) s = fmaf(ws[k], vb[(size_t)k * kD + tid], s);
    opart[(size_t)(chunk * kB + b) * kD + tid] = s;
}

__global__ __launch_bounds__(256)
void out_reduce_kernel(const float* __restrict__ opart, float* __restrict__ out)
{
    const int i = blockIdx.x * 256 + threadIdx.x;
    float s = 0.0f;
#pragma unroll
    for (int c = 0; c < N_KCHUNK; c++) s += opart[(size_t)c * (kB * kD) + i];
    out[i] = s * (1.0f / (float)kS);
}

// ---------------------------------------------------------------------------
// Launch
// ---------------------------------------------------------------------------
extern "C" void kernel_launch(void* const* d_in, const int* in_sizes, int n_in,
                              void* d_out, int out_size)
{
    const float* nodes = (const float*)d_in[0];
    const int*   mask  = (const int*)  d_in[1];
    const float* Wq    = (const float*)d_in[2];
    const float* bq    = (const float*)d_in[3];
    const float* Wk    = (const float*)d_in[4];
    const float* bk    = (const float*)d_in[5];
    const float* Wv    = (const float*)d_in[6];
    const float* bv    = (const float*)d_in[7];
    float* out = (float*)d_out;

    float *Nb, *Wh, *Wl, *Qb, *Kb, *V, *rpart, *wpart, *opart;
    __nv_bfloat16* E;
    cudaGetSymbolAddress((void**)&Nb,    g_Nb);
    cudaGetSymbolAddress((void**)&Wh,    g_Wh);
    cudaGetSymbolAddress((void**)&Wl,    g_Wl);
    cudaGetSymbolAddress((void**)&Qb,    g_Qb);
    cudaGetSymbolAddress((void**)&Kb,    g_Kb);
    cudaGetSymbolAddress((void**)&V,     g_V);
    cudaGetSymbolAddress((void**)&E,     g_E);
    cudaGetSymbolAddress((void**)&rpart, g_rpart);
    cudaGetSymbolAddress((void**)&wpart, g_wpart);
    cudaGetSymbolAddress((void**)&opart, g_opart);

    cudaFuncSetAttribute(proj_gemm,
                         cudaFuncAttributeMaxDynamicSharedMemorySize, PJ_SMEM);
    cudaFuncSetAttribute(score_gemm,
                         cudaFuncAttributeMaxDynamicSharedMemorySize, SC_SMEM);

    dim3 blk(256);

    // 0. Prep: nodes -> blocked tf32; weights -> blocked hi/lo split.
    nodes_prep<<<dim3(8, kM / 128), blk>>>(nodes, Nb);
    wsplit_prep<<<dim3(8, 2, 3), blk>>>(Wq, Wk, Wv, Wh, Wl);

    // 1. Projections: grid (2 nx, 128 my, 3 w), 2 CTAs/SM.
    dim3 gproj(2, kM / 128, 3);
    proj_gemm<<<gproj, blk, PJ_SMEM>>>(Nb, Wh, Wl, bq, bk, bv, Qb, Kb, V);

    // 2. Scores (2-CTA cluster, K multicast): grid (16 my, 8 nx, 8 bz).
    dim3 gsc(kS / 128, kS / 256, kB);
    score_gemm<<<gsc, blk, SC_SMEM>>>(Qb, Kb, mask, E, rpart, 0.0625f);

    // 3. colsum (inline invr), fused w-reduce + output contraction.
    colsum_stream_kernel<<<dim3(QCH, kB), blk>>>(E, rpart, wpart);
    out_part_kernel<<<dim3(N_KCHUNK, kB), blk>>>(wpart, V, opart);
    out_reduce_kernel<<<(kB * kD) / 256, blk>>>(opart, out);
}